// round 17
// baseline (speedup 1.0000x reference)
#include <cuda_runtime.h>

#define NN 4
#define AA 8732
#define CC 81
#define TPB 256
#define NPOST 35                 /* post units per batch */
#define APB 128                  /* anchors per prep unit (2 thr/anchor) */
#define NPREP 69                 /* prep units per batch */
#define G (NPREP * NN)           /* 276 blocks, all resident at 2/SM */
#define JC 128                   /* g-boxes per iou chunk */
#define NJ 69                    /* chunks per batch */
#define NCH (NJ * NN)            /* 276 chunk units */
#define NUNITS (NCH + NN)        /* + 4 select units */

// ---------------- scratch (device globals: allocation-free) ----------------
__device__ float4 g_pbox[NN * AA];
__device__ float4 g_gbox[NN * AA];
__device__ float  g_parea[NN * AA];
__device__ float  g_garea[NN * AA];
__device__ float  g_validf[NN * AA];
__device__ float  g_con[NN * AA];
__device__ float  g_conneg[NN * AA];
__device__ float  g_sl1[NN * AA];
__device__ float  g_ioup[NJ][NN * AA];
__device__ int    g_plist[NN * AA];
__device__ int    g_cnt[NN];         // zero-init; reset by last block
__device__ int    g_pos[NN];
__device__ unsigned g_thr[NN];
__device__ float  g_part1[NN * NPOST];
__device__ float  g_part2[NN * NPOST];
__device__ int    g_bar1, g_bar2, g_done;   // zero-init; reset by last block

__global__ void __launch_bounds__(TPB, 2) k_all(
    const float* __restrict__ ploc, const float* __restrict__ plabel,
    const float* __restrict__ gloc, const int* __restrict__ glabel,
    const float* __restrict__ dbox, float* __restrict__ out)
{
    int bx = blockIdx.x;
    int t  = threadIdx.x;

    __shared__ union {
        struct { float se[TPB]; float xg[APB]; } a;          // prep
        struct { float4 gb[JC]; float ga[JC]; } b;           // iou chunk
        struct { int hist[256]; int suf[256]; } sel;         // radix select
        struct { float r1[TPB]; float r2[TPB]; } c;          // post reduce
    } sh;
    __shared__ unsigned s_prefix;
    __shared__ int s_rem;
    __shared__ int s_last;
    __shared__ float s_val[NN];

    // ================= Phase A: per-anchor prep (1 unit/block) =============
    {
        int n   = bx / NPREP;
        int blk = bx % NPREP;
        int la = t & (APB - 1);
        int half = t >> 7;
        int a = blk * APB + la;
        bool act = (a < AA);

        int lab = 0;
        float se = 0.f;
        if (act) {
            lab = glabel[n * AA + a];
            const float* pp = plabel + (size_t)n * CC * AA + a;
            int c0 = half ? 41 : 0;
            int c1 = half ? CC : 41;
            #pragma unroll 8
            for (int c = c0; c < c1; c++) se += __expf(pp[(size_t)c * AA]);
            if ((lab >= 41) == (half == 1)) sh.a.xg[la] = pp[(size_t)lab * AA];
        }
        sh.a.se[t] = se;
        __syncthreads();

        if (act && half == 0) {
            float con = __logf(sh.a.se[la] + sh.a.se[la + APB]) - sh.a.xg[la];

            float dx = dbox[0 * AA + a], dy = dbox[1 * AA + a];
            float dw = dbox[2 * AA + a], dh = dbox[3 * AA + a];
            const float* pl = ploc + (size_t)n * 4 * AA;
            const float* gg = gloc + (size_t)n * 4 * AA;
            float px = pl[a], py = pl[AA + a], pw = pl[2 * AA + a], ph = pl[3 * AA + a];
            float gx = gg[a], gy = gg[AA + a], gw = gg[2 * AA + a], gh = gg[3 * AA + a];

            float gxt = 10.0f * (gx - dx) / dw;
            float gyt = 10.0f * (gy - dy) / dh;
            float gwt = 5.0f * __logf(gw / dw);
            float ght = 5.0f * __logf(gh / dh);

            float s = 0.f, d, ad;
            d = px - gxt; ad = fabsf(d); s += (ad < 1.f) ? 0.5f * d * d : ad - 0.5f;
            d = py - gyt; ad = fabsf(d); s += (ad < 1.f) ? 0.5f * d * d : ad - 0.5f;
            d = pw - gwt; ad = fabsf(d); s += (ad < 1.f) ? 0.5f * d * d : ad - 0.5f;
            d = ph - ght; ad = fabsf(d); s += (ad < 1.f) ? 0.5f * d * d : ad - 0.5f;

            float pcx = 0.1f * px * dw + dx, pcy = 0.1f * py * dh + dy;
            float pww = __expf(0.2f * pw) * dw, phh = __expf(0.2f * ph) * dh;
            float plx = pcx - 0.5f * pww, pty = pcy - 0.5f * phh;
            float prx = pcx + 0.5f * pww, pby = pcy + 0.5f * phh;
            float gcx = 0.1f * gx * dw + dx, gcy = 0.1f * gy * dh + dy;
            float gww = __expf(0.2f * gw) * dw, ghh = __expf(0.2f * gh) * dh;
            float glx = gcx - 0.5f * gww, gty = gcy - 0.5f * ghh;
            float grx = gcx + 0.5f * gww, gby = gcy + 0.5f * ghh;

            float pa = (prx - plx) * (pby - pty);
            float ga = (grx - glx) * (gby - gty);
            int valid = (plx < prx) && (pty < pby);

            int id = n * AA + a;
            g_pbox[id] = make_float4(plx, pty, prx, pby);
            g_gbox[id] = make_float4(glx, gty, grx, gby);
            g_parea[id] = pa;
            g_garea[id] = ga;
            g_validf[id] = valid ? 1.f : 0.f;
            g_con[id] = con;
            g_conneg[id] = (lab > 0) ? 0.f : con;
            g_sl1[id] = s;

            if (lab > 0) {
                int idx = atomicAdd(&g_cnt[n], 1);
                g_plist[n * AA + idx] = a;
            }
        }
    }

    // ---- grid barrier 1 (arrive: RMW once; wait: volatile LOAD poll) ------
    __syncthreads();
    __threadfence();
    if (t == 0) {
        atomicAdd(&g_bar1, 1);
        while (*(volatile int*)&g_bar1 < G) __nanosleep(64);
    }
    __syncthreads();

    // ================= Phase B: iou chunk units + select units =============
    for (int u = bx; u < NUNITS; u += G) {
        if (u < NCH) {
            int n = u / NJ;
            int c = u % NJ;

            if (t < JC) {
                int j = c * JC + t;
                if (j < AA) {
                    sh.b.gb[t] = g_gbox[n * AA + j];
                    sh.b.ga[t] = g_garea[n * AA + j];
                } else {
                    sh.b.gb[t] = make_float4(1e30f, 1e30f, 1e30f, 1e30f);
                    sh.b.ga[t] = 1.0f;
                }
            }
            __syncthreads();

            int cnt = __ldcg(&g_cnt[n]);
            for (int slot = t; slot < cnt; slot += TPB) {
                int aid = g_plist[n * AA + slot];
                float4 pb = g_pbox[n * AA + aid];
                float pa = g_parea[n * AA + aid];

                float a0 = 0.f, a1 = 0.f, a2 = 0.f, a3 = 0.f;
                #pragma unroll 8
                for (int uu = 0; uu < JC; uu++) {
                    float4 gb = sh.b.gb[uu];
                    float ga = sh.b.ga[uu];
                    float x1 = fmaxf(pb.x, gb.x);
                    float x2 = fminf(pb.z, gb.z);
                    float y1 = fmaxf(pb.y, gb.y);
                    float y2 = fminf(pb.w, gb.w);
                    float iw = fmaxf(x2 - x1, 0.f);
                    float ih = fmaxf(y2 - y1, 0.f);
                    float inter = iw * ih;
                    float ua = fmaf(inter, -1.0f, pa + ga);
                    float r;
                    asm("rcp.approx.f32 %0, %1;" : "=f"(r) : "f"(ua));
                    float v = inter * r;
                    switch (uu & 3) {
                        case 0: a0 += v; break;
                        case 1: a1 += v; break;
                        case 2: a2 += v; break;
                        default: a3 += v; break;
                    }
                }
                g_ioup[c][n * AA + aid] = (a0 + a1) + (a2 + a3);
            }
            __syncthreads();   // protect shared reuse by next unit
        } else {
            // ---- radix select: exact K-th largest of conneg bits ----
            int n = u - NCH;
            int pos = __ldcg(&g_cnt[n]);
            int K = min(3 * pos, AA);
            if (t == 0) { g_pos[n] = pos; s_prefix = 0; s_rem = K; }
            __syncthreads();
            if (K <= 0) {
                if (t == 0) g_thr[n] = 0xFFFFFFFFu;
                __syncthreads();
                continue;
            }
            for (int pass = 0; pass < 4; pass++) {
                int shift = 24 - 8 * pass;
                sh.sel.hist[t] = 0;
                __syncthreads();
                unsigned pref = s_prefix;
                int rem = s_rem;
                for (int i = t; i < 9216; i += TPB) {
                    bool ok = (i < AA);
                    unsigned bits = 0;
                    if (ok) {
                        bits = __float_as_uint(g_conneg[n * AA + i]);
                        if (pass > 0 && (bits >> (shift + 8)) != pref) ok = false;
                    }
                    int bin = ok ? (int)((bits >> shift) & 0xFF) : (256 + (t & 31));
                    unsigned mm = __match_any_sync(0xffffffffu, bin);
                    if (ok && (t & 31) == (__ffs(mm) - 1)) atomicAdd(&sh.sel.hist[bin], __popc(mm));
                }
                __syncthreads();
                sh.sel.suf[t] = sh.sel.hist[t];
                __syncthreads();
                for (int st = 1; st < 256; st <<= 1) {
                    int v = sh.sel.suf[t] + ((t + st < 256) ? sh.sel.suf[t + st] : 0);
                    __syncthreads();
                    sh.sel.suf[t] = v;
                    __syncthreads();
                }
                int gt = (t < 255) ? sh.sel.suf[t + 1] : 0;
                if (sh.sel.suf[t] >= rem && gt < rem) {
                    s_prefix = (pref << 8) | (unsigned)t;
                    s_rem = rem - gt;
                }
                __syncthreads();
            }
            if (t == 0) g_thr[n] = s_prefix;
            __syncthreads();
        }
    }

    // ---- grid barrier 2 ----
    __syncthreads();
    __threadfence();
    if (t == 0) {
        atomicAdd(&g_bar2, 1);
        while (*(volatile int*)&g_bar2 < G) __nanosleep(64);
    }
    __syncthreads();

    // ================= Phase C: epilogue (140 units) + final ===============
    if (bx < NN * NPOST) {
        int n   = bx / NPOST;
        int blk = bx % NPOST;
        int i = blk * TPB + t;

        float a1 = 0.f, a2 = 0.f;
        unsigned thr = __ldcg(&g_thr[n]);
        if (i < AA) {
            int id = n * AA + i;
            float con = g_con[id];
            float cn = g_conneg[id];
            int lab = glabel[id];

            if (lab > 0) {
                float iou = 0.f;
                #pragma unroll
                for (int s = 0; s < NJ; s++) iou += g_ioup[s][id];
                float sl1 = g_sl1[id];
                float vld = g_validf[id];
                float w = (vld != 0.f) ? 0.01f * iou : 0.f;
                a1 = sl1 / (sl1 + w) * sl1;
            }
            float nm = (__float_as_uint(cn) >= thr) ? 1.f : 0.f;
            float mm = (lab > 0) ? 1.f : 0.f;
            a2 = con * (mm + nm);
        }

        sh.c.r1[t] = a1; sh.c.r2[t] = a2;
        __syncthreads();
        for (int sd = TPB / 2; sd > 0; sd >>= 1) {
            if (t < sd) { sh.c.r1[t] += sh.c.r1[t + sd]; sh.c.r2[t] += sh.c.r2[t + sd]; }
            __syncthreads();
        }
        if (t == 0) {
            g_part1[n * NPOST + blk] = sh.c.r1[0];
            g_part2[n * NPOST + blk] = sh.c.r2[0];
        }
    }

    // elected-last block does the deterministic final reduce
    __syncthreads();
    if (t == 0) {
        __threadfence();
        int prev = atomicAdd(&g_done, 1);
        s_last = (prev == G - 1) ? 1 : 0;
    }
    __syncthreads();

    if (s_last) {
        int w = t >> 5, lane = t & 31;
        if (w < NN) {
            float s1 = 0.f, s2 = 0.f;
            for (int b = lane; b < NPOST; b += 32) {
                s1 += g_part1[w * NPOST + b];
                s2 += g_part2[w * NPOST + b];
            }
            float v = s1 + s2;
            #pragma unroll
            for (int o = 16; o > 0; o >>= 1) v += __shfl_down_sync(0xffffffffu, v, o);
            if (lane == 0) {
                int pos = __ldcg(&g_pos[w]);
                s_val[w] = (pos > 0) ? v / fmaxf((float)pos, 1e-6f) : 0.f;
            }
        }
        __syncthreads();
        if (t == 0) {
            out[0] = (s_val[0] + s_val[1] + s_val[2] + s_val[3]) * 0.25f;
            // reset for next graph replay (this block is provably last)
            g_bar1 = 0; g_bar2 = 0; g_done = 0;
            #pragma unroll
            for (int nn = 0; nn < NN; nn++) g_cnt[nn] = 0;
        }
    }
}

// ---------------- launch ----------------
extern "C" void kernel_launch(void* const* d_in, const int* in_sizes, int n_in,
                              void* d_out, int out_size)
{
    const float* ploc   = (const float*)d_in[0];
    const float* plabel = (const float*)d_in[1];
    const float* gloc   = (const float*)d_in[2];
    const int*   glabel = (const int*)d_in[3];
    const float* dbox   = (const float*)d_in[4];
    float* out = (float*)d_out;

    k_all<<<G, TPB>>>(ploc, plabel, gloc, glabel, dbox, out);
}